// round 1
// baseline (speedup 1.0000x reference)
#include <cuda_runtime.h>

#define BATCH 32
#define HH 19
#define WW 19
#define HW 361
#define H2 38
#define HW2 1444
#define C1IN 512
#define C1OUT 64
#define CR 256
#define C2IN 1280
#define C2OUT 1024
#define CMROWS 600
#define KD 1024
#define BN_EPS 1e-5f
#define SLOPE 0.1f

// ---------------- scratch (device globals; no allocation allowed) ----------------
__device__ float g_x1r[BATCH * CR * HW];          // reorg output (b,256,19,19)
__device__ float g_pre[BATCH * C2OUT * HW];       // conv2 output (b,1024,19,19)
__device__ float g_w1t[C1IN * C1OUT];             // w1 transposed [ic][oc], scale-folded
__device__ float g_w2t[C2IN * 9 * C2OUT];         // w2 transposed [ic*9+kk][oc], scale-folded
__device__ float g_wct[KD * CMROWS];              // meta weights transposed [k][cm]
__device__ float g_cb[CMROWS];                    // meta bias [cm]

// ---------------- prep: fold BN scale into weights, transpose ----------------
__global__ void fold_w1(const float* __restrict__ w1, const float* __restrict__ g1,
                        const float* __restrict__ v1) {
    int idx = blockIdx.x * blockDim.x + threadIdx.x;
    if (idx >= C1IN * C1OUT) return;
    int ic = idx >> 6, oc = idx & 63;
    float s = g1[oc] / sqrtf(v1[oc] + BN_EPS);
    g_w1t[idx] = w1[oc * C1IN + ic] * s;
}

__global__ void fold_w2(const float* __restrict__ w2, const float* __restrict__ g2,
                        const float* __restrict__ v2) {
    int idx = blockIdx.x * blockDim.x + threadIdx.x;
    if (idx >= C2IN * 9 * C2OUT) return;
    int oc = idx & 1023, k = idx >> 10;              // k = ic*9 + kk
    float s = g2[oc] / sqrtf(v2[oc] + BN_EPS);
    g_w2t[idx] = w2[oc * (C2IN * 9) + k] * s;
}

__global__ void fold_meta(const float* __restrict__ meta) {
    int idx = blockIdx.x * blockDim.x + threadIdx.x;
    if (idx < KD * CMROWS) {
        int cm = idx % CMROWS, k = idx / CMROWS;
        g_wct[idx] = meta[cm * 1025 + k];
    } else if (idx < KD * CMROWS + CMROWS) {
        int cm = idx - KD * CMROWS;
        g_cb[cm] = meta[cm * 1025 + 1024];
    }
}

// ---------------- conv1x1 + BN + leaky + reorg ----------------
// GEMM per batch: (64 oc x 512 ic) x (512 ic x 1444 pos). Tile 64oc x 64pos, 4x4 micro.
__global__ __launch_bounds__(256) void conv1_kernel(
    const float* __restrict__ s5, const float* __restrict__ g1,
    const float* __restrict__ b1, const float* __restrict__ m1,
    const float* __restrict__ v1) {
    __shared__ float in_s[16][64];
    __shared__ float w_s[16][64];
    int b = blockIdx.y;
    int p0 = blockIdx.x * 64;
    int tid = threadIdx.x;
    int tx = tid & 15, ty = tid >> 4;
    float acc[4][4] = {};

    for (int ic0 = 0; ic0 < C1IN; ic0 += 16) {
#pragma unroll
        for (int r = 0; r < 4; r++) {
            int e = tid + r * 256;
            int ic = e >> 6, q = e & 63;
            int pos = p0 + q;
            in_s[ic][q] = (pos < HW2) ? s5[((b * C1IN) + (ic0 + ic)) * HW2 + pos] : 0.f;
            w_s[ic][q] = g_w1t[(ic0 + ic) * 64 + q];
        }
        __syncthreads();
#pragma unroll
        for (int k = 0; k < 16; k++) {
            float4 av = *(const float4*)&in_s[k][tx * 4];
            float4 wv = *(const float4*)&w_s[k][ty * 4];
            float a[4] = {av.x, av.y, av.z, av.w};
            float w[4] = {wv.x, wv.y, wv.z, wv.w};
#pragma unroll
            for (int i = 0; i < 4; i++)
#pragma unroll
                for (int j = 0; j < 4; j++) acc[i][j] += w[i] * a[j];
        }
        __syncthreads();
    }

#pragma unroll
    for (int i = 0; i < 4; i++) {
        int oc = ty * 4 + i;
        float s = g1[oc] / sqrtf(v1[oc] + BN_EPS);
        float sh = b1[oc] - m1[oc] * s;
#pragma unroll
        for (int j = 0; j < 4; j++) {
            int pos = p0 + tx * 4 + j;
            if (pos < HW2) {
                float v = acc[i][j] + sh;
                v = v > 0.f ? v : SLOPE * v;
                int py = pos / H2, px = pos % H2;
                int oc2 = (py & 1) * 128 + (px & 1) * 64 + oc;   // reorg channel
                g_x1r[((b * CR) + oc2) * HW + (py >> 1) * WW + (px >> 1)] = v;
            }
        }
    }
}

// ---------------- conv3x3 (implicit GEMM) + BN + leaky ----------------
// Tile: 128 oc x 64 flattened positions; K = 1280 ic x 9 taps, chunked 8 ic.
// Input patch (8 ic x 7 rows x 21 cols, halo+zeropad) in smem; weights [ic*9+kk][128 oc].
__global__ __launch_bounds__(256) void conv2_kernel(
    const float* __restrict__ s6, const float* __restrict__ g2,
    const float* __restrict__ b2, const float* __restrict__ m2,
    const float* __restrict__ v2) {
    __shared__ float ins[8][148];       // 7*21 = 147 used
    __shared__ float ws[8 * 9 * 128];
    int b = blockIdx.z;
    int o0 = blockIdx.y * 128;
    int p0 = blockIdx.x * 64;
    int y0 = p0 / 19 - 1;               // patch row 0 maps to image row y0
    int tid = threadIdx.x;
    int tx = tid & 15, ty = tid >> 4;

    int base[4];
    bool valid[4];
#pragma unroll
    for (int j = 0; j < 4; j++) {
        int pos = p0 + tx * 4 + j;
        if (pos < HW) {
            valid[j] = true;
            base[j] = (pos / 19 - y0) * 21 + pos % 19;
        } else {
            valid[j] = false;
            base[j] = 42;               // safe dummy inside patch
        }
    }

    float acc[8][4] = {};

    for (int ic0 = 0; ic0 < C2IN; ic0 += 8) {
        // load input patch (reads reorg buffer for ch<256 else stage6)
        for (int e = tid; e < 8 * 147; e += 256) {
            int ic = e / 147, r = e % 147;
            int row = r / 21, col = r % 21;
            int y = y0 + row, x = col - 1;
            float v = 0.f;
            if ((unsigned)y < 19u && (unsigned)x < 19u) {
                int ch = ic0 + ic;
                v = (ch < CR) ? g_x1r[((b * CR) + ch) * HW + y * WW + x]
                              : s6[((b * C2OUT) + (ch - CR)) * HW + y * WW + x];
            }
            ins[ic][row * 21 + col] = v;
        }
        // load weight slab: 8 ic x 9 taps x 128 oc (coalesced from transposed layout)
#pragma unroll
        for (int r = 0; r < 36; r++) {
            int e = tid + r * 256;
            ws[e] = g_w2t[(ic0 * 9 + (e >> 7)) * C2OUT + o0 + (e & 127)];
        }
        __syncthreads();

#pragma unroll 2
        for (int ic = 0; ic < 8; ic++) {
#pragma unroll
            for (int kk = 0; kk < 9; kk++) {
                const int koff = (kk / 3 - 1) * 21 + (kk % 3);
                float a[4];
#pragma unroll
                for (int j = 0; j < 4; j++) a[j] = ins[ic][base[j] + koff];
                const float* wp = &ws[(ic * 9 + kk) * 128 + ty * 8];
                float4 w0 = *(const float4*)wp;
                float4 w1v = *(const float4*)(wp + 4);
                float wv[8] = {w0.x, w0.y, w0.z, w0.w, w1v.x, w1v.y, w1v.z, w1v.w};
#pragma unroll
                for (int i = 0; i < 8; i++)
#pragma unroll
                    for (int j = 0; j < 4; j++) acc[i][j] += wv[i] * a[j];
            }
        }
        __syncthreads();
    }

#pragma unroll
    for (int i = 0; i < 8; i++) {
        int oc = o0 + ty * 8 + i;
        float s = g2[oc] / sqrtf(v2[oc] + BN_EPS);
        float sh = b2[oc] - m2[oc] * s;
#pragma unroll
        for (int j = 0; j < 4; j++) {
            if (valid[j]) {
                int pos = p0 + tx * 4 + j;
                float v = acc[i][j] + sh;
                v = v > 0.f ? v : SLOPE * v;
                g_pre[((b * C2OUT) + oc) * HW + pos] = v;
            }
        }
    }
}

// ---------------- classifier head: out[b,cm,p] = cls_w[cm,:] . pre[b,:,p] + cb[cm] ----------------
__global__ __launch_bounds__(256) void head_kernel(float* __restrict__ out) {
    __shared__ float a_s[16][64];
    __shared__ float b_s[16][64];
    int b = blockIdx.z;
    int cm0 = blockIdx.y * 64;
    int p0 = blockIdx.x * 64;
    int tid = threadIdx.x;
    int tx = tid & 15, ty = tid >> 4;
    float acc[4][4] = {};

    for (int k0 = 0; k0 < KD; k0 += 16) {
#pragma unroll
        for (int r = 0; r < 4; r++) {
            int e = tid + r * 256;
            int k = e >> 6, q = e & 63;
            int cm = cm0 + q;
            a_s[k][q] = (cm < CMROWS) ? g_wct[(k0 + k) * CMROWS + cm] : 0.f;
            int pos = p0 + q;
            b_s[k][q] = (pos < HW) ? g_pre[((b * C2OUT) + (k0 + k)) * HW + pos] : 0.f;
        }
        __syncthreads();
#pragma unroll
        for (int k = 0; k < 16; k++) {
            float4 av = *(const float4*)&a_s[k][ty * 4];
            float4 bv = *(const float4*)&b_s[k][tx * 4];
            float a[4] = {av.x, av.y, av.z, av.w};
            float bb[4] = {bv.x, bv.y, bv.z, bv.w};
#pragma unroll
            for (int i = 0; i < 4; i++)
#pragma unroll
                for (int j = 0; j < 4; j++) acc[i][j] += a[i] * bb[j];
        }
        __syncthreads();
    }

#pragma unroll
    for (int i = 0; i < 4; i++) {
        int cm = cm0 + ty * 4 + i;
        if (cm >= CMROWS) continue;
        float bias = g_cb[cm];
#pragma unroll
        for (int j = 0; j < 4; j++) {
            int pos = p0 + tx * 4 + j;
            if (pos < HW) out[((b * CMROWS) + cm) * HW + pos] = acc[i][j] + bias;
        }
    }
}

// ---------------- launch ----------------
extern "C" void kernel_launch(void* const* d_in, const int* in_sizes, int n_in,
                              void* d_out, int out_size) {
    const float* s6 = (const float*)d_in[0];
    const float* s5 = (const float*)d_in[1];
    const float* w1 = (const float*)d_in[2];
    const float* g1 = (const float*)d_in[3];
    const float* b1 = (const float*)d_in[4];
    const float* m1 = (const float*)d_in[5];
    const float* v1 = (const float*)d_in[6];
    const float* w2 = (const float*)d_in[7];
    const float* g2 = (const float*)d_in[8];
    const float* b2 = (const float*)d_in[9];
    const float* m2 = (const float*)d_in[10];
    const float* v2 = (const float*)d_in[11];
    const float* meta = (const float*)d_in[12];
    float* out = (float*)d_out;

    fold_w1<<<(C1IN * C1OUT + 255) / 256, 256>>>(w1, g1, v1);
    fold_w2<<<(C2IN * 9 * C2OUT + 255) / 256, 256>>>(w2, g2, v2);
    fold_meta<<<(KD * CMROWS + CMROWS + 255) / 256, 256>>>(meta);

    conv1_kernel<<<dim3(23, BATCH), 256>>>(s5, g1, b1, m1, v1);
    conv2_kernel<<<dim3(6, 8, BATCH), 256>>>(s6, g2, b2, m2, v2);
    head_kernel<<<dim3(6, 10, BATCH), 256>>>(out);
}

// round 5
// speedup vs baseline: 2.7414x; 2.7414x over previous
#include <cuda_runtime.h>

#define BATCH 32
#define HW 361
#define H2 38
#define HW2 1444
#define C1IN 512
#define C1OUT 64
#define CR 256
#define C2IN 1280
#define C2OUT 1024
#define CMROWS 600
#define KD 1024
#define BN_EPS 1e-5f
#define SLOPE 0.1f

#define W2S_TOT (160 * 9 * 64 * 128)   // swizzled conv2 weights
#define WCS_TOT (128 * 40 * 128)       // swizzled head weights (640 cm padded)

// ---------------- scratch ----------------
__device__ __align__(16) float g_x1r[BATCH * CR * HW];
__device__ __align__(16) float g_pre[BATCH * C2OUT * HW];
__device__ __align__(16) float g_w1t[C1IN * C1OUT];
__device__ __align__(16) float g_w2s[W2S_TOT];
__device__ __align__(16) float g_wcs[WCS_TOT];
__device__ float g_cb[CMROWS];

__device__ __forceinline__ float to_tf32(float v) {
    unsigned uv;
    asm("cvt.rna.tf32.f32 %0, %1;" : "=r"(uv) : "f"(v));
    return __uint_as_float(uv);
}

// ---------------- prep ----------------
__global__ void fold_w1(const float* __restrict__ w1, const float* __restrict__ g1,
                        const float* __restrict__ v1) {
    int idx = blockIdx.x * blockDim.x + threadIdx.x;
    if (idx >= C1IN * C1OUT) return;
    int ic = idx >> 6, oc = idx & 63;
    float s = g1[oc] * rsqrtf(v1[oc] + BN_EPS);
    g_w1t[idx] = w1[oc * C1IN + ic] * s;
}

// swizzle conv2 weights into m16n8k8 A-fragment order, fold BN scale, round to tf32
// layout: g_w2s[((c*9+kk)*64 + ocb)*128 + lane*4 + reg]
__global__ void fold_w2(const float* __restrict__ w2, const float* __restrict__ g2,
                        const float* __restrict__ v2) {
    int idx = blockIdx.x * blockDim.x + threadIdx.x;
    if (idx >= W2S_TOT) return;
    int reg = idx & 3, lane = (idx >> 2) & 31;
    int ocb = (idx >> 7) & 63;
    int r2 = idx >> 13;
    int kk = r2 % 9, c = r2 / 9;
    int g = lane >> 2, t = lane & 3;
    int oc = (ocb << 4) + g + ((reg & 1) << 3);
    int ic = (c << 3) + t + ((reg >> 1) << 2);
    float s = g2[oc] * rsqrtf(v2[oc] + BN_EPS);
    g_w2s[idx] = to_tf32(w2[(oc * C2IN + ic) * 9 + kk] * s);
}

// swizzle head weights: g_wcs[(c8*40 + cmb)*128 + lane*4 + reg], plus bias
__global__ void fold_meta(const float* __restrict__ meta) {
    int idx = blockIdx.x * blockDim.x + threadIdx.x;
    if (idx < WCS_TOT) {
        int reg = idx & 3, lane = (idx >> 2) & 31;
        int cmb = (idx >> 7) % 40;
        int c8 = (idx >> 7) / 40;
        int g = lane >> 2, t = lane & 3;
        int cm = (cmb << 4) + g + ((reg & 1) << 3);
        int k = (c8 << 3) + t + ((reg >> 1) << 2);
        float v = (cm < CMROWS) ? meta[cm * 1025 + k] : 0.f;
        g_wcs[idx] = to_tf32(v);
    } else if (idx < WCS_TOT + CMROWS) {
        int cm = idx - WCS_TOT;
        g_cb[cm] = meta[cm * 1025 + 1024];
    }
}

// ---------------- conv1x1 + BN + leaky + reorg (FFMA, small) ----------------
__global__ __launch_bounds__(256) void conv1_kernel(
    const float* __restrict__ s5, const float* __restrict__ g1,
    const float* __restrict__ b1, const float* __restrict__ m1,
    const float* __restrict__ v1) {
    __shared__ float in_s[16][64];
    __shared__ float w_s[16][64];
    int b = blockIdx.y;
    int p0 = blockIdx.x * 64;
    int tid = threadIdx.x;
    int tx = tid & 15, ty = tid >> 4;
    float acc[4][4] = {};

    for (int ic0 = 0; ic0 < C1IN; ic0 += 16) {
#pragma unroll
        for (int r = 0; r < 4; r++) {
            int e = tid + r * 256;
            int ic = e >> 6, q = e & 63;
            int pos = p0 + q;
            in_s[ic][q] = (pos < HW2) ? s5[((b * C1IN) + (ic0 + ic)) * HW2 + pos] : 0.f;
            w_s[ic][q] = g_w1t[(ic0 + ic) * 64 + q];
        }
        __syncthreads();
#pragma unroll
        for (int k = 0; k < 16; k++) {
            float4 av = *(const float4*)&in_s[k][tx * 4];
            float4 wv = *(const float4*)&w_s[k][ty * 4];
            float a[4] = {av.x, av.y, av.z, av.w};
            float w[4] = {wv.x, wv.y, wv.z, wv.w};
#pragma unroll
            for (int i = 0; i < 4; i++)
#pragma unroll
                for (int j = 0; j < 4; j++) acc[i][j] += w[i] * a[j];
        }
        __syncthreads();
    }

#pragma unroll
    for (int i = 0; i < 4; i++) {
        int oc = ty * 4 + i;
        float s = g1[oc] * rsqrtf(v1[oc] + BN_EPS);
        float sh = b1[oc] - m1[oc] * s;
#pragma unroll
        for (int j = 0; j < 4; j++) {
            int pos = p0 + tx * 4 + j;
            if (pos < HW2) {
                float v = acc[i][j] + sh;
                v = v > 0.f ? v : SLOPE * v;
                int py = pos / H2, px = pos % H2;
                int oc2 = (py & 1) * 128 + (px & 1) * 64 + oc;
                g_x1r[((b * CR) + oc2) * HW + (py >> 1) * 19 + (px >> 1)] = v;
            }
        }
    }
}

// ---------------- conv3x3 implicit GEMM on tensor pipe (tf32 mma.sync) ----------------
// block: 128 oc x 64 pos; 8 warps = 4(oc) x 2(pos); warp tile 32oc x 32pos
// K: 160 chunks of 8 ic, each chunk = 9 taps x k8 mma
#define INS_STRIDE 168   // %32 == 8 -> conflict-free quad-k access
__global__ __launch_bounds__(256) void conv2_mma(
    const float* __restrict__ s6, const float* __restrict__ g2,
    const float* __restrict__ b2, const float* __restrict__ m2,
    const float* __restrict__ v2) {
    __shared__ __align__(16) float ws[9 * 8 * 128];
    __shared__ float ins[8][INS_STRIDE];
    int b = blockIdx.z, o0 = blockIdx.y << 7, p0 = blockIdx.x << 6;
    int y0 = p0 / 19 - 1;
    int tid = threadIdx.x, lane = tid & 31, warp = tid >> 5;
    int wo = warp >> 1, wp = warp & 1;
    int g = lane >> 2, t = lane & 3;
    int ocb0 = o0 >> 4;

    int basep[4];
#pragma unroll
    for (int nt = 0; nt < 4; nt++) {
        int pos = p0 + wp * 32 + nt * 8 + g;
        basep[nt] = (pos < HW) ? (pos / 19 - y0) * 21 + pos % 19 : 42;
    }

    float acc[2][4][4] = {};

    for (int c = 0; c < 160; c++) {
        // stage input patch: 8 ic x 7 rows x 21 cols (halo + zero-pad), tf32-rounded
        for (int e = tid; e < 8 * 147; e += 256) {
            int ic = e / 147, r = e - ic * 147;
            int row = r / 21, col = r - row * 21;
            int y = y0 + row, x = col - 1;
            float v = 0.f;
            if ((unsigned)y < 19u && (unsigned)x < 19u) {
                int ch = (c << 3) + ic;
                v = (ch < CR) ? g_x1r[((b << 8) + ch) * HW + y * 19 + x]
                              : s6[((b << 10) + (ch - CR)) * HW + y * 19 + x];
            }
            ins[ic][row * 21 + col] = to_tf32(v);
        }
        // stage weights: 9 kk x 8 ocb x 128 (fragment-ordered), float4 copy
#pragma unroll
        for (int r = 0; r < 9; r++) {
            int f4 = tid + (r << 8);
            int kk = f4 >> 8;
            int rem = f4 & 255;
            int ocb_l = rem >> 5, w4 = rem & 31;
            ((float4*)ws)[f4] =
                ((const float4*)g_w2s)[((c * 9 + kk) * 64 + ocb0 + ocb_l) * 32 + w4];
        }
        __syncthreads();

#pragma unroll
        for (int kk = 0; kk < 9; kk++) {
            const int koff = (kk / 3 - 1) * 21 + (kk % 3);
            float4 afr[2];
            afr[0] = *(const float4*)&ws[((kk << 3) + wo * 2 + 0) * 128 + (lane << 2)];
            afr[1] = *(const float4*)&ws[((kk << 3) + wo * 2 + 1) * 128 + (lane << 2)];
#pragma unroll
            for (int nt = 0; nt < 4; nt++) {
                unsigned b0 = __float_as_uint(ins[t][basep[nt] + koff]);
                unsigned b1 = __float_as_uint(ins[t + 4][basep[nt] + koff]);
#pragma unroll
                for (int mt = 0; mt < 2; mt++) {
                    asm volatile(
                        "mma.sync.aligned.m16n8k8.row.col.f32.tf32.tf32.f32 "
                        "{%0,%1,%2,%3}, {%4,%5,%6,%7}, {%8,%9}, {%0,%1,%2,%3};\n"
                        : "+f"(acc[mt][nt][0]), "+f"(acc[mt][nt][1]),
                          "+f"(acc[mt][nt][2]), "+f"(acc[mt][nt][3])
                        : "r"(__float_as_uint(afr[mt].x)), "r"(__float_as_uint(afr[mt].y)),
                          "r"(__float_as_uint(afr[mt].z)), "r"(__float_as_uint(afr[mt].w)),
                          "r"(b0), "r"(b1));
                }
            }
        }
        __syncthreads();
    }

#pragma unroll
    for (int mt = 0; mt < 2; mt++) {
        int oc_base = o0 + wo * 32 + mt * 16 + g;
#pragma unroll
        for (int rr = 0; rr < 2; rr++) {
            int oc = oc_base + rr * 8;
            float s = g2[oc] * rsqrtf(v2[oc] + BN_EPS);
            float sh = b2[oc] - m2[oc] * s;
#pragma unroll
            for (int nt = 0; nt < 4; nt++) {
                int pos = p0 + wp * 32 + nt * 8 + 2 * t;
#pragma unroll
                for (int cc = 0; cc < 2; cc++) {
                    if (pos + cc < HW) {
                        float v = acc[mt][nt][rr * 2 + cc] + sh;
                        v = v > 0.f ? v : SLOPE * v;
                        g_pre[((b << 10) + oc) * HW + pos + cc] = v;
                    }
                }
            }
        }
    }
}

// ---------------- head GEMM on tensor pipe ----------------
// block: 128 cm x 64 pos; K = 1024 in 32 chunks of 32
#define PCS_STRIDE 72   // %32 == 8
__global__ __launch_bounds__(256) void head_mma(float* __restrict__ out) {
    __shared__ __align__(16) float wcs[4 * 8 * 128];
    __shared__ float pcs[32][PCS_STRIDE];
    int b = blockIdx.z, cm0 = blockIdx.y << 7, p0 = blockIdx.x << 6;
    int tid = threadIdx.x, lane = tid & 31, warp = tid >> 5;
    int wm = warp >> 1, wp = warp & 1;
    int g = lane >> 2, t = lane & 3;
    int cmb0 = cm0 >> 4;

    float acc[2][4][4] = {};

    for (int c = 0; c < 32; c++) {
        for (int e = tid; e < 2048; e += 256) {
            int k = e >> 6, q = e & 63;
            int pos = p0 + q;
            float v = (pos < HW) ? g_pre[((b << 10) + (c << 5) + k) * HW + pos] : 0.f;
            pcs[k][q] = to_tf32(v);
        }
#pragma unroll
        for (int r = 0; r < 4; r++) {
            int f4 = tid + (r << 8);
            int kst = f4 >> 8, rem = f4 & 255;
            int cmb_l = rem >> 5, w4 = rem & 31;
            ((float4*)wcs)[f4] =
                ((const float4*)g_wcs)[(((c << 2) + kst) * 40 + cmb0 + cmb_l) * 32 + w4];
        }
        __syncthreads();

#pragma unroll
        for (int kst = 0; kst < 4; kst++) {
            float4 afr[2];
            afr[0] = *(const float4*)&wcs[((kst << 3) + wm * 2 + 0) * 128 + (lane << 2)];
            afr[1] = *(const float4*)&wcs[((kst << 3) + wm * 2 + 1) * 128 + (lane << 2)];
#pragma unroll
            for (int nt = 0; nt < 4; nt++) {
                int n = wp * 32 + nt * 8 + g;
                unsigned b0 = __float_as_uint(pcs[kst * 8 + t][n]);
                unsigned b1 = __float_as_uint(pcs[kst * 8 + t + 4][n]);
#pragma unroll
                for (int mt = 0; mt < 2; mt++) {
                    asm volatile(
                        "mma.sync.aligned.m16n8k8.row.col.f32.tf32.tf32.f32 "
                        "{%0,%1,%2,%3}, {%4,%5,%6,%7}, {%8,%9}, {%0,%1,%2,%3};\n"
                        : "+f"(acc[mt][nt][0]), "+f"(acc[mt][nt][1]),
                          "+f"(acc[mt][nt][2]), "+f"(acc[mt][nt][3])
                        : "r"(__float_as_uint(afr[mt].x)), "r"(__float_as_uint(afr[mt].y)),
                          "r"(__float_as_uint(afr[mt].z)), "r"(__float_as_uint(afr[mt].w)),
                          "r"(b0), "r"(b1));
                }
            }
        }
        __syncthreads();
    }

#pragma unroll
    for (int mt = 0; mt < 2; mt++) {
#pragma unroll
        for (int rr = 0; rr < 2; rr++) {
            int cm = cm0 + wm * 32 + mt * 16 + g + rr * 8;
            if (cm >= CMROWS) continue;
            float bias = g_cb[cm];
#pragma unroll
            for (int nt = 0; nt < 4; nt++) {
                int pos = p0 + wp * 32 + nt * 8 + 2 * t;
#pragma unroll
                for (int cc = 0; cc < 2; cc++) {
                    if (pos + cc < HW)
                        out[((b * CMROWS) + cm) * HW + pos + cc] =
                            acc[mt][nt][rr * 2 + cc] + bias;
                }
            }
        }
    }
}

// ---------------- launch ----------------
extern "C" void kernel_launch(void* const* d_in, const int* in_sizes, int n_in,
                              void* d_out, int out_size) {
    const float* s6 = (const float*)d_in[0];
    const float* s5 = (const float*)d_in[1];
    const float* w1 = (const float*)d_in[2];
    const float* g1 = (const float*)d_in[3];
    const float* b1 = (const float*)d_in[4];
    const float* m1 = (const float*)d_in[5];
    const float* v1 = (const float*)d_in[6];
    const float* w2 = (const float*)d_in[7];
    const float* g2 = (const float*)d_in[8];
    const float* b2 = (const float*)d_in[9];
    const float* m2 = (const float*)d_in[10];
    const float* v2 = (const float*)d_in[11];
    const float* meta = (const float*)d_in[12];
    float* out = (float*)d_out;

    fold_w1<<<(C1IN * C1OUT + 255) / 256, 256>>>(w1, g1, v1);
    fold_w2<<<(W2S_TOT + 255) / 256, 256>>>(w2, g2, v2);
    fold_meta<<<(WCS_TOT + CMROWS + 255) / 256, 256>>>(meta);

    conv1_kernel<<<dim3(23, BATCH), 256>>>(s5, g1, b1, m1, v1);
    conv2_mma<<<dim3(6, 8, BATCH), 256>>>(s6, g2, b2, m2, v2);
    head_mma<<<dim3(6, 5, BATCH), 256>>>(out);
}

// round 9
// speedup vs baseline: 5.2164x; 1.9029x over previous
#include <cuda_runtime.h>
#include <cuda_fp16.h>

#define BATCH 32
#define HW 361
#define H2 38
#define HW2 1444
#define C1IN 512
#define C1OUT 64
#define CR 256
#define C2IN 1280
#define C2OUT 1024
#define CMROWS 600
#define KD 1024
#define BN_EPS 1e-5f
#define SLOPE 0.1f

// fp16 fragment-packed weights:
// conv2: 80 ic-chunks(16) x 9 taps x 64 oc-groups(16) x 32 lanes x (uint4 = 4 half2 regs)
#define W2S_U4 (80 * 9 * 64 * 32)
#define W2S_U  (W2S_U4 * 4)
// head: 64 k-chunks(16) x 40 cm-groups(16, 640 padded) x 32 lanes x uint4
#define WCS_U4 (64 * 40 * 32)
#define WCS_U  (WCS_U4 * 4)

// ---------------- scratch ----------------
__device__ __align__(16) float g_x1r[BATCH * CR * HW];
__device__ __align__(16) float g_pre[BATCH * C2OUT * HW];
__device__ __align__(16) float g_w1t[C1IN * C1OUT];
__device__ __align__(16) uint4 g_w2s4[W2S_U4];
__device__ __align__(16) uint4 g_wcs4[WCS_U4];
__device__ float g_cb[CMROWS];

__device__ __forceinline__ unsigned pack_h2(float a, float b) {
    __half2 h = __floats2half2_rn(a, b);
    return *(unsigned*)&h;
}

// ---------------- prep ----------------
__global__ void fold_w1(const float* __restrict__ w1, const float* __restrict__ g1,
                        const float* __restrict__ v1) {
    int idx = blockIdx.x * blockDim.x + threadIdx.x;
    if (idx >= C1IN * C1OUT) return;
    int ic = idx >> 6, oc = idx & 63;
    float s = g1[oc] * rsqrtf(v1[oc] + BN_EPS);
    g_w1t[idx] = w1[oc * C1IN + ic] * s;
}

// conv2 weights -> m16n8k16 A-fragment order (half2 regs), BN folded.
// uint layout: [((c*9+kk)*64 + ocb)*128 + lane*4 + reg]
__global__ void fold_w2(const float* __restrict__ w2, const float* __restrict__ g2,
                        const float* __restrict__ v2) {
    int idx = blockIdx.x * blockDim.x + threadIdx.x;
    if (idx >= W2S_U) return;
    int reg = idx & 3, lane = (idx >> 2) & 31;
    int ocb = (idx >> 7) & 63;
    int r2 = idx >> 13;
    int kk = r2 % 9, c = r2 / 9;
    int g = lane >> 2, t = lane & 3;
    int oc = (ocb << 4) + g + ((reg & 1) << 3);
    int ic0 = (c << 4) + 2 * t + ((reg >> 1) << 3);
    float s = g2[oc] * rsqrtf(v2[oc] + BN_EPS);
    float a = w2[(oc * C2IN + ic0) * 9 + kk] * s;
    float b = w2[(oc * C2IN + ic0 + 1) * 9 + kk] * s;
    ((unsigned*)g_w2s4)[idx] = pack_h2(a, b);
}

// head weights -> A-fragment order; uint layout [(kc*40 + cmb)*128 + lane*4 + reg]
__global__ void fold_meta(const float* __restrict__ meta) {
    int idx = blockIdx.x * blockDim.x + threadIdx.x;
    if (idx < WCS_U) {
        int reg = idx & 3, lane = (idx >> 2) & 31;
        int cmb = (idx >> 7) % 40;
        int kc = (idx >> 7) / 40;
        int g = lane >> 2, t = lane & 3;
        int cm = (cmb << 4) + g + ((reg & 1) << 3);
        int k0 = (kc << 4) + 2 * t + ((reg >> 1) << 3);
        float a = 0.f, b = 0.f;
        if (cm < CMROWS) {
            a = meta[cm * 1025 + k0];
            b = meta[cm * 1025 + k0 + 1];
        }
        ((unsigned*)g_wcs4)[idx] = pack_h2(a, b);
    } else if (idx < WCS_U + CMROWS) {
        int cm = idx - WCS_U;
        g_cb[cm] = meta[cm * 1025 + 1024];
    }
}

// ---------------- conv1x1 + BN + leaky + reorg (FFMA, small) ----------------
__global__ __launch_bounds__(256) void conv1_kernel(
    const float* __restrict__ s5, const float* __restrict__ g1,
    const float* __restrict__ b1, const float* __restrict__ m1,
    const float* __restrict__ v1) {
    __shared__ float in_s[16][64];
    __shared__ float w_s[16][64];
    int b = blockIdx.y;
    int p0 = blockIdx.x * 64;
    int tid = threadIdx.x;
    int tx = tid & 15, ty = tid >> 4;
    float acc[4][4] = {};

    for (int ic0 = 0; ic0 < C1IN; ic0 += 16) {
#pragma unroll
        for (int r = 0; r < 4; r++) {
            int e = tid + r * 256;
            int ic = e >> 6, q = e & 63;
            int pos = p0 + q;
            in_s[ic][q] = (pos < HW2) ? s5[((b * C1IN) + (ic0 + ic)) * HW2 + pos] : 0.f;
            w_s[ic][q] = g_w1t[(ic0 + ic) * 64 + q];
        }
        __syncthreads();
#pragma unroll
        for (int k = 0; k < 16; k++) {
            float4 av = *(const float4*)&in_s[k][tx * 4];
            float4 wv = *(const float4*)&w_s[k][ty * 4];
            float a[4] = {av.x, av.y, av.z, av.w};
            float w[4] = {wv.x, wv.y, wv.z, wv.w};
#pragma unroll
            for (int i = 0; i < 4; i++)
#pragma unroll
                for (int j = 0; j < 4; j++) acc[i][j] += w[i] * a[j];
        }
        __syncthreads();
    }

#pragma unroll
    for (int i = 0; i < 4; i++) {
        int oc = ty * 4 + i;
        float s = g1[oc] * rsqrtf(v1[oc] + BN_EPS);
        float sh = b1[oc] - m1[oc] * s;
#pragma unroll
        for (int j = 0; j < 4; j++) {
            int pos = p0 + tx * 4 + j;
            if (pos < HW2) {
                float v = acc[i][j] + sh;
                v = v > 0.f ? v : SLOPE * v;
                int py = pos / H2, px = pos % H2;
                int oc2 = (py & 1) * 128 + (px & 1) * 64 + oc;
                g_x1r[((b * CR) + oc2) * HW + (py >> 1) * 19 + (px >> 1)] = v;
            }
        }
    }
}

// ---------------- conv3x3 implicit GEMM, fp16 m16n8k16 ----------------
// block: 128 oc x 64 pos; 8 warps = 4(oc) x 2(pos); warp tile 32oc x 32pos
// K: 80 chunks of 16 ic; per chunk 9 taps x (K=16) mma
#define INS_STRIDE 168   // half2 units; %32 == 8 -> conflict-free
__global__ __launch_bounds__(256) void conv2_mma(
    const float* __restrict__ s6, const float* __restrict__ g2,
    const float* __restrict__ b2, const float* __restrict__ m2,
    const float* __restrict__ v2) {
    __shared__ __align__(16) uint4 ws4[9 * 8 * 32];          // 36.9KB
    __shared__ unsigned ins2[8][INS_STRIDE];                 // 5.4KB (ic-pairs as half2)
    int b = blockIdx.z, o0 = blockIdx.y << 7, p0 = blockIdx.x << 6;
    int y0 = p0 / 19 - 1;
    int tid = threadIdx.x, lane = tid & 31, warp = tid >> 5;
    int wo = warp >> 1, wp = warp & 1;
    int g = lane >> 2, t = lane & 3;
    int ocb0 = o0 >> 4;

    int basep[4];
#pragma unroll
    for (int nt = 0; nt < 4; nt++) {
        int pos = p0 + wp * 32 + nt * 8 + g;
        basep[nt] = (pos < HW) ? (pos / 19 - y0) * 21 + pos % 19 : 42;
    }

    float acc[2][4][4] = {};

    for (int c = 0; c < 80; c++) {
        // stage input patch: 8 ic-pairs x 7 rows x 21 cols, half2-packed
        for (int e = tid; e < 8 * 147; e += 256) {
            int icp = e / 147, r = e - icp * 147;
            int row = r / 21, col = r - row * 21;
            int y = y0 + row, x = col - 1;
            float v0 = 0.f, v1 = 0.f;
            if ((unsigned)y < 19u && (unsigned)x < 19u) {
                int ch = (c << 4) + 2 * icp;
                if (ch < CR) {
                    const float* p = &g_x1r[((b << 8) + ch) * HW + y * 19 + x];
                    v0 = p[0]; v1 = p[HW];
                } else {
                    const float* p = &s6[((b << 10) + (ch - CR)) * HW + y * 19 + x];
                    v0 = p[0]; v1 = p[HW];
                }
            }
            ins2[icp][row * 21 + col] = pack_h2(v0, v1);
        }
        // stage weights: 9 kk x 8 ocb x 32 lanes (uint4 each)
#pragma unroll
        for (int r = 0; r < 9; r++) {
            int f4 = tid + (r << 8);
            int kk = f4 >> 8;
            int rem = f4 & 255;
            int ocb_l = rem >> 5, w4 = rem & 31;
            ws4[f4] = g_w2s4[((c * 9 + kk) * 64 + ocb0 + ocb_l) * 32 + w4];
        }
        __syncthreads();

#pragma unroll
        for (int kk = 0; kk < 9; kk++) {
            const int koff = (kk / 3 - 1) * 21 + (kk % 3);
            uint4 afr[2];
            afr[0] = ws4[(kk << 3) * 32 + (wo * 2 + 0) * 32 + lane];
            afr[1] = ws4[(kk << 3) * 32 + (wo * 2 + 1) * 32 + lane];
#pragma unroll
            for (int nt = 0; nt < 4; nt++) {
                unsigned b0 = ins2[t][basep[nt] + koff];
                unsigned b1 = ins2[t + 4][basep[nt] + koff];
#pragma unroll
                for (int mt = 0; mt < 2; mt++) {
                    asm volatile(
                        "mma.sync.aligned.m16n8k16.row.col.f32.f16.f16.f32 "
                        "{%0,%1,%2,%3}, {%4,%5,%6,%7}, {%8,%9}, {%0,%1,%2,%3};\n"
                        : "+f"(acc[mt][nt][0]), "+f"(acc[mt][nt][1]),
                          "+f"(acc[mt][nt][2]), "+f"(acc[mt][nt][3])
                        : "r"(afr[mt].x), "r"(afr[mt].y),
                          "r"(afr[mt].z), "r"(afr[mt].w),
                          "r"(b0), "r"(b1));
                }
            }
        }
        __syncthreads();
    }

#pragma unroll
    for (int mt = 0; mt < 2; mt++) {
        int oc_base = o0 + wo * 32 + mt * 16 + g;
#pragma unroll
        for (int rr = 0; rr < 2; rr++) {
            int oc = oc_base + rr * 8;
            float s = g2[oc] * rsqrtf(v2[oc] + BN_EPS);
            float sh = b2[oc] - m2[oc] * s;
#pragma unroll
            for (int nt = 0; nt < 4; nt++) {
                int pos = p0 + wp * 32 + nt * 8 + 2 * t;
#pragma unroll
                for (int cc = 0; cc < 2; cc++) {
                    if (pos + cc < HW) {
                        float v = acc[mt][nt][rr * 2 + cc] + sh;
                        v = v > 0.f ? v : SLOPE * v;
                        g_pre[((b << 10) + oc) * HW + pos + cc] = v;
                    }
                }
            }
        }
    }
}

// ---------------- head GEMM, fp16 m16n8k16 ----------------
// block: 128 cm x 64 pos; K = 1024 in 32 chunks of 32 (2 x K16 mma)
#define PCS_STRIDE 72   // half2 units; %32 == 8
__global__ __launch_bounds__(256) void head_mma(float* __restrict__ out) {
    __shared__ __align__(16) uint4 wcs4[2 * 8 * 32];         // 8.2KB
    __shared__ unsigned pcs2[16][PCS_STRIDE];                // 4.6KB (k-pairs)
    int b = blockIdx.z, cm0 = blockIdx.y << 7, p0 = blockIdx.x << 6;
    int tid = threadIdx.x, lane = tid & 31, warp = tid >> 5;
    int wm = warp >> 1, wp = warp & 1;
    int g = lane >> 2, t = lane & 3;
    int cmb0 = cm0 >> 4;

    float acc[2][4][4] = {};

    for (int c = 0; c < 32; c++) {
        // stage 32 k x 64 pos as half2 k-pairs
        for (int e = tid; e < 1024; e += 256) {
            int kp = e >> 6, q = e & 63;
            int pos = p0 + q;
            float v0 = 0.f, v1 = 0.f;
            if (pos < HW) {
                const float* p = &g_pre[((b << 10) + (c << 5) + 2 * kp) * HW + pos];
                v0 = p[0]; v1 = p[HW];
            }
            pcs2[kp][q] = pack_h2(v0, v1);
        }
#pragma unroll
        for (int r = 0; r < 2; r++) {
            int f4 = tid + (r << 8);
            int kst = f4 >> 8, rem = f4 & 255;
            int cmb_l = rem >> 5, w4 = rem & 31;
            wcs4[f4] = g_wcs4[((c * 2 + kst) * 40 + cmb0 + cmb_l) * 32 + w4];
        }
        __syncthreads();

#pragma unroll
        for (int kst = 0; kst < 2; kst++) {
            uint4 afr[2];
            afr[0] = wcs4[(kst << 3) * 32 + (wm * 2 + 0) * 32 + lane];
            afr[1] = wcs4[(kst << 3) * 32 + (wm * 2 + 1) * 32 + lane];
#pragma unroll
            for (int nt = 0; nt < 4; nt++) {
                int n = wp * 32 + nt * 8 + g;
                unsigned b0 = pcs2[kst * 8 + t][n];
                unsigned b1 = pcs2[kst * 8 + t + 4][n];
#pragma unroll
                for (int mt = 0; mt < 2; mt++) {
                    asm volatile(
                        "mma.sync.aligned.m16n8k16.row.col.f32.f16.f16.f32 "
                        "{%0,%1,%2,%3}, {%4,%5,%6,%7}, {%8,%9}, {%0,%1,%2,%3};\n"
                        : "+f"(acc[mt][nt][0]), "+f"(acc[mt][nt][1]),
                          "+f"(acc[mt][nt][2]), "+f"(acc[mt][nt][3])
                        : "r"(afr[mt].x), "r"(afr[mt].y),
                          "r"(afr[mt].z), "r"(afr[mt].w),
                          "r"(b0), "r"(b1));
                }
            }
        }
        __syncthreads();
    }

#pragma unroll
    for (int mt = 0; mt < 2; mt++) {
#pragma unroll
        for (int rr = 0; rr < 2; rr++) {
            int cm = cm0 + wm * 32 + mt * 16 + g + rr * 8;
            if (cm >= CMROWS) continue;
            float bias = g_cb[cm];
#pragma unroll
            for (int nt = 0; nt < 4; nt++) {
                int pos = p0 + wp * 32 + nt * 8 + 2 * t;
#pragma unroll
                for (int cc = 0; cc < 2; cc++) {
                    if (pos + cc < HW)
                        out[((b * CMROWS) + cm) * HW + pos + cc] =
                            acc[mt][nt][rr * 2 + cc] + bias;
                }
            }
        }
    }
}

// ---------------- launch ----------------
extern "C" void kernel_launch(void* const* d_in, const int* in_sizes, int n_in,
                              void* d_out, int out_size) {
    const float* s6 = (const float*)d_in[0];
    const float* s5 = (const float*)d_in[1];
    const float* w1 = (const float*)d_in[2];
    const float* g1 = (const float*)d_in[3];
    const float* b1 = (const float*)d_in[4];
    const float* m1 = (const float*)d_in[5];
    const float* v1 = (const float*)d_in[6];
    const float* w2 = (const float*)d_in[7];
    const float* g2 = (const float*)d_in[8];
    const float* b2 = (const float*)d_in[9];
    const float* m2 = (const float*)d_in[10];
    const float* v2 = (const float*)d_in[11];
    const float* meta = (const float*)d_in[12];
    float* out = (float*)d_out;

    fold_w1<<<(C1IN * C1OUT + 255) / 256, 256>>>(w1, g1, v1);
    fold_w2<<<(W2S_U + 255) / 256, 256>>>(w2, g2, v2);
    fold_meta<<<(WCS_U + CMROWS + 255) / 256, 256>>>(meta);

    conv1_kernel<<<dim3(23, BATCH), 256>>>(s5, g1, b1, m1, v1);
    conv2_mma<<<dim3(6, 8, BATCH), 256>>>(s6, g2, b2, m2, v2);
    head_mma<<<dim3(6, 5, BATCH), 256>>>(out);
}